// round 11
// baseline (speedup 1.0000x reference)
#include <cuda_runtime.h>
#include <math.h>
#include <stdint.h>

#define G 64      // B*T graphs
#define NN 1024   // nodes per graph
#define FF 64     // features
#define WP 72     // smem pitch (floats) for B tiles -> conflict-free LDS
#define AP 36     // adj smem pitch (words): 144B, 16B-aligned

// Scratch (device globals: allocation-free rule)
__device__ float g_Wh[G * NN * FF];   // 16 MB (tf32-rounded)
__device__ float g_s1[G * NN];
__device__ float g_s2[G * NN];

__device__ __forceinline__ float f2tf32(float x) {
    float r;
    asm("cvt.rna.tf32.f32 %0, %1;" : "=f"(r) : "f"(x));
    return r;
}
__device__ __forceinline__ uint32_t smem_u32(const void* p) {
    uint32_t a;
    asm("{ .reg .u64 t; cvta.to.shared.u64 t, %1; cvt.u32.u64 %0, t; }"
        : "=r"(a) : "l"(p));
    return a;
}
#define CP_ASYNC16(dst, src) \
    asm volatile("cp.async.cg.shared.global [%0], [%1], 16;" \
                 :: "r"(dst), "l"(src) : "memory")
#define CP_COMMIT() asm volatile("cp.async.commit_group;" ::: "memory")
#define CP_WAIT(n)  asm volatile("cp.async.wait_group %0;" :: "n"(n) : "memory")

#define MMA_TF32(acc, a0, a1, a2, a3, b0, b1) \
    asm volatile( \
        "mma.sync.aligned.m16n8k8.row.col.f32.tf32.tf32.f32 " \
        "{%0,%1,%2,%3}, {%4,%5,%6,%7}, {%8,%9}, {%0,%1,%2,%3};" \
        : "+f"((acc)[0]), "+f"((acc)[1]), "+f"((acc)[2]), "+f"((acc)[3]) \
        : "r"(a0), "r"(a1), "r"(a2), "r"(a3), "r"(b0), "r"(b1))

// ---------------------------------------------------------------------------
// Kernel P: Wh = h @ W via mma.sync (tf32-rounded); s1 = Wh@a1, s2 = Wh@a2.
// ---------------------------------------------------------------------------
__global__ __launch_bounds__(256) void prep_kernel(const float* __restrict__ h,
                                                   const float* __restrict__ W,
                                                   const float* __restrict__ a) {
    __shared__ float Ws[64 * WP];
    __shared__ float sA[128];

    const int tid  = threadIdx.x;
    const int lane = tid & 31;
    const int w    = tid >> 5;

    #pragma unroll
    for (int i = 0; i < 16; i++) {
        int idx = tid + i * 256;
        int k = idx >> 6, f = idx & 63;
        Ws[k * WP + f] = f2tf32(W[idx]);
    }
    if (tid < 128) sA[tid] = a[tid];
    __syncthreads();

    const int gq = lane >> 2;
    const int t  = lane & 3;
    const int r0 = blockIdx.x * 128 + w * 16 + gq;
    const int r1 = r0 + 8;
    const float* h0 = h + (size_t)r0 * FF;
    const float* h1 = h + (size_t)r1 * FF;

    float acc[8][4];
    #pragma unroll
    for (int nt = 0; nt < 8; nt++)
        #pragma unroll
        for (int q = 0; q < 4; q++) acc[nt][q] = 0.f;

    #pragma unroll
    for (int ks = 0; ks < 8; ks++) {
        const int kb = ks * 8 + t;
        const uint32_t a0 = __float_as_uint(f2tf32(h0[kb]));
        const uint32_t a1 = __float_as_uint(f2tf32(h1[kb]));
        const uint32_t a2 = __float_as_uint(f2tf32(h0[kb + 4]));
        const uint32_t a3 = __float_as_uint(f2tf32(h1[kb + 4]));
        #pragma unroll
        for (int nt = 0; nt < 8; nt++) {
            const uint32_t b0 = __float_as_uint(Ws[kb * WP + nt * 8 + gq]);
            const uint32_t b1 = __float_as_uint(Ws[(kb + 4) * WP + nt * 8 + gq]);
            MMA_TF32(acc[nt], a0, a1, a2, a3, b0, b1);
        }
    }

    float s1_0 = 0.f, s2_0 = 0.f, s1_1 = 0.f, s2_1 = 0.f;
    float* o0 = g_Wh + (size_t)r0 * FF + 2 * t;
    float* o1 = g_Wh + (size_t)r1 * FF + 2 * t;
    #pragma unroll
    for (int nt = 0; nt < 8; nt++) {
        const int c = nt * 8 + 2 * t;
        const float a1c0 = sA[c],      a1c1 = sA[c + 1];
        const float a2c0 = sA[64 + c], a2c1 = sA[64 + c + 1];
        s1_0 += acc[nt][0] * a1c0 + acc[nt][1] * a1c1;
        s2_0 += acc[nt][0] * a2c0 + acc[nt][1] * a2c1;
        s1_1 += acc[nt][2] * a1c0 + acc[nt][3] * a1c1;
        s2_1 += acc[nt][2] * a2c0 + acc[nt][3] * a2c1;
        *(float2*)(o0 + nt * 8) = make_float2(f2tf32(acc[nt][0]), f2tf32(acc[nt][1]));
        *(float2*)(o1 + nt * 8) = make_float2(f2tf32(acc[nt][2]), f2tf32(acc[nt][3]));
    }
    #pragma unroll
    for (int off = 1; off <= 2; off <<= 1) {
        s1_0 += __shfl_xor_sync(0xffffffffu, s1_0, off);
        s2_0 += __shfl_xor_sync(0xffffffffu, s2_0, off);
        s1_1 += __shfl_xor_sync(0xffffffffu, s1_1, off);
        s2_1 += __shfl_xor_sync(0xffffffffu, s2_1, off);
    }
    if (t == 0) {
        g_s1[r0] = s1_0; g_s2[r0] = s2_0;
        g_s1[r1] = s1_1; g_s2[r1] = s2_1;
    }
}

// ---------------------------------------------------------------------------
// Kernel C: out[128,64] per CTA, mma.sync m16n8k8 tf32, j-PERMUTED chunks:
// slot k = ks*8+u  <->  j = j0 + 4u + ks  (bijection on 0..31).
// Per chunk: adj tile (128x32 ints) cp.async-staged one chunk ahead
// (single buffer, freed by LDS->reg+pack before restage); Wh tiles
// double-buffered with the SAME row permutation; Z via ones-column tile.
// ---------------------------------------------------------------------------
// dynamic smem (bytes):
//  tab2  float2[1024] @ 0      (8192)   {e^{s2}, e^{0.2 s2}}
//  adjS  u32[128*AP]  @ 8192   (18432)
//  Whs0  f32[32*WP]   @ 26624  (9216)
//  Whs1  f32[32*WP]   @ 35840  (9216)   total 45056
#define OFF_TAB  0
#define OFF_ADJ  8192
#define OFF_WHS0 26624
#define OFF_WHS1 35840
#define ATTN_SMEM 45056

extern __shared__ char smc[];

__global__ __launch_bounds__(256, 4) void attn_mma(const int* __restrict__ adj,
                                                   float* __restrict__ out) {
    float2*   tab2 = (float2*)(smc + OFF_TAB);
    const uint32_t* adjS = (const uint32_t*)(smc + OFF_ADJ);
    const uint32_t sb = smem_u32(smc);

    const int tid  = threadIdx.x;
    const int lane = tid & 31;
    const int w    = tid >> 5;
    const int gq   = lane >> 2;
    const int t    = lane & 3;
    const int gr   = blockIdx.x >> 3;
    const int i0   = (blockIdx.x & 7) << 7;

    const float* Whg  = g_Wh + (size_t)gr * NN * FF;
    const int*   adjg = adj + ((size_t)gr * NN + i0) * NN;
    const uint32_t whoff[2] = { OFF_WHS0, OFF_WHS1 };

    // ---- prologue: stage adj(0) + Wh(0); build exp table
    {
        const int r = tid >> 1, sg = (tid & 1) * 4;
        #pragma unroll
        for (int q = 0; q < 4; q++)
            CP_ASYNC16(sb + OFF_ADJ + (uint32_t)(r * AP + (sg + q) * 4) * 4,
                       adjg + (size_t)r * NN + (sg + q) * 4);
        #pragma unroll
        for (int q = 0; q < 2; q++) {
            int idx = tid + q * 256;
            int k = idx >> 4, s4 = (idx & 15) * 4;
            int srow = (k & 7) * 4 + (k >> 3);          // permuted source row
            CP_ASYNC16(sb + OFF_WHS0 + (uint32_t)(k * WP + s4) * 4,
                       Whg + (size_t)srow * FF + s4);
        }
        CP_COMMIT();
        const float4 s2v = ((const float4*)(g_s2 + (size_t)gr * NN))[tid];
        tab2[tid * 4 + 0] = make_float2(__expf(s2v.x), __expf(0.2f * s2v.x));
        tab2[tid * 4 + 1] = make_float2(__expf(s2v.y), __expf(0.2f * s2v.y));
        tab2[tid * 4 + 2] = make_float2(__expf(s2v.z), __expf(0.2f * s2v.z));
        tab2[tid * 4 + 3] = make_float2(__expf(s2v.w), __expf(0.2f * s2v.w));
    }

    const int lr0 = w * 16 + gq;
    const int lr1 = lr0 + 8;
    const float s1_0 = g_s1[(size_t)gr * NN + i0 + lr0];
    const float s1_1 = g_s1[(size_t)gr * NN + i0 + lr1];
    const float e1_0 = __expf(s1_0), e1b_0 = __expf(0.2f * s1_0);
    const float e1_1 = __expf(s1_1), e1b_1 = __expf(0.2f * s1_1);
    const float et0 = 1.0f / e1_0;   // e^{-s1_0}; s2 > -s1 <=> e^{s2} > et
    const float et1 = 1.0f / e1_1;

    float acc[9][4];
    #pragma unroll
    for (int nt = 0; nt < 9; nt++)
        #pragma unroll
        for (int q = 0; q < 4; q++) acc[nt][q] = 0.f;
    const uint32_t bz = (gq == 0) ? 0x3f800000u : 0u;   // ones-column B frag

    CP_WAIT(0);
    __syncthreads();

    for (int jc = 0; jc < 32; jc++) {
        // step 1: adj tile -> regs -> packed bitmasks (frees adj buffer)
        int4 v0a = *(const int4*)(adjS + lr0 * AP + t * 4);
        int4 v0b = *(const int4*)(adjS + lr0 * AP + 16 + t * 4);
        int4 v1a = *(const int4*)(adjS + lr1 * AP + t * 4);
        int4 v1b = *(const int4*)(adjS + lr1 * AP + 16 + t * 4);
        // adj values are exactly 0/1 (randint(0,2)) -> pack by value
        const uint32_t m0 = (uint32_t)(v0a.x | (v0a.y << 1) | (v0a.z << 2) | (v0a.w << 3)
                         | (v0b.x << 4) | (v0b.y << 5) | (v0b.z << 6) | (v0b.w << 7));
        const uint32_t m1 = (uint32_t)(v1a.x | (v1a.y << 1) | (v1a.z << 2) | (v1a.w << 3)
                         | (v1b.x << 4) | (v1b.y << 5) | (v1b.z << 6) | (v1b.w << 7));
        __syncthreads();   // all threads read adjS & finished prev-parity Wh buf

        // step 2: stage chunk jc+1 (adj single buffer, Wh other parity)
        if (jc < 31) {
            const int j0n = (jc + 1) * 32;
            const int r = tid >> 1, sg = (tid & 1) * 4;
            #pragma unroll
            for (int q = 0; q < 4; q++)
                CP_ASYNC16(sb + OFF_ADJ + (uint32_t)(r * AP + (sg + q) * 4) * 4,
                           adjg + (size_t)r * NN + j0n + (sg + q) * 4);
            const uint32_t dstb = sb + whoff[(jc + 1) & 1];
            #pragma unroll
            for (int q = 0; q < 2; q++) {
                int idx = tid + q * 256;
                int k = idx >> 4, s4 = (idx & 15) * 4;
                int srow = j0n + (k & 7) * 4 + (k >> 3);
                CP_ASYNC16(dstb + (uint32_t)(k * WP + s4) * 4,
                           Whg + (size_t)srow * FF + s4);
            }
            CP_COMMIT();
        }

        // step 3: compute chunk jc
        const float* Wc = (const float*)(smc + whoff[jc & 1]);
        const int jt = jc * 32 + 4 * t;

        #pragma unroll
        for (int ks = 0; ks < 4; ks++) {
            const int kb = ks * 8 + t;
            const float2 ta = tab2[jt + ks];        // j = j0+4t+ks
            const float2 tb = tab2[jt + 16 + ks];   // j = j0+4t+16+ks

            const bool c00 = ta.x > et0, c01 = tb.x > et0;
            const bool c10 = ta.x > et1, c11 = tb.x > et1;
            float p00 = c00 ? e1_0 * ta.x : e1b_0 * ta.y;
            float p01 = c01 ? e1_0 * tb.x : e1b_0 * tb.y;
            float p10 = c10 ? e1_1 * ta.x : e1b_1 * ta.y;
            float p11 = c11 ? e1_1 * tb.x : e1b_1 * tb.y;
            p00 = (m0 & (1u << ks))       ? p00 : 0.f;
            p01 = (m0 & (16u << ks))      ? p01 : 0.f;
            p10 = (m1 & (1u << ks))       ? p10 : 0.f;
            p11 = (m1 & (16u << ks))      ? p11 : 0.f;

            const uint32_t a0 = __float_as_uint(p00);
            const uint32_t a1 = __float_as_uint(p10);
            const uint32_t a2 = __float_as_uint(p01);
            const uint32_t a3 = __float_as_uint(p11);

            #pragma unroll
            for (int nt = 0; nt < 8; nt++) {
                const uint32_t b0 = __float_as_uint(Wc[kb * WP + nt * 8 + gq]);
                const uint32_t b1 = __float_as_uint(Wc[(kb + 4) * WP + nt * 8 + gq]);
                MMA_TF32(acc[nt], a0, a1, a2, a3, b0, b1);
            }
            MMA_TF32(acc[8], a0, a1, a2, a3, bz, bz);   // Z tile
        }

        // step 4: copies for jc+1 landed during compute; make visible
        if (jc < 31) { CP_WAIT(0); }
        __syncthreads();
    }

    // Z = col 64 (ones tile), held by t==0 lanes; broadcast within quad
    const float Z0 = __shfl_sync(0xffffffffu, acc[8][0], lane & 28);
    const float Z1 = __shfl_sync(0xffffffffu, acc[8][2], lane & 28);
    const float inv0 = 1.0f / Z0;
    const float inv1 = 1.0f / Z1;

    float* o0 = out + ((size_t)gr * NN + i0 + lr0) * FF + 2 * t;
    float* o1 = out + ((size_t)gr * NN + i0 + lr1) * FF + 2 * t;
    #pragma unroll
    for (int nt = 0; nt < 8; nt++) {
        float e0 = acc[nt][0] * inv0;
        float e1 = acc[nt][1] * inv0;
        float e2 = acc[nt][2] * inv1;
        float e3 = acc[nt][3] * inv1;
        e0 = e0 > 0.f ? e0 : expm1f(e0);
        e1 = e1 > 0.f ? e1 : expm1f(e1);
        e2 = e2 > 0.f ? e2 : expm1f(e2);
        e3 = e3 > 0.f ? e3 : expm1f(e3);
        *(float2*)(o0 + nt * 8) = make_float2(e0, e1);
        *(float2*)(o1 + nt * 8) = make_float2(e2, e3);
    }
}

// ---------------------------------------------------------------------------
extern "C" void kernel_launch(void* const* d_in, const int* in_sizes, int n_in,
                              void* d_out, int out_size) {
    const float* h   = (const float*)d_in[0];
    const int*   adj = (const int*)d_in[1];
    const float* W   = (const float*)d_in[2];
    const float* a   = (const float*)d_in[3];
    float* out = (float*)d_out;

    cudaFuncSetAttribute(attn_mma, cudaFuncAttributeMaxDynamicSharedMemorySize,
                         ATTN_SMEM);

    prep_kernel<<<512, 256>>>(h, W, a);
    attn_mma<<<G * 8, 256, ATTN_SMEM>>>(adj, out);
}

// round 12
// speedup vs baseline: 1.1769x; 1.1769x over previous
#include <cuda_runtime.h>
#include <math.h>
#include <stdint.h>

#define G 64      // B*T graphs
#define NN 1024   // nodes per graph
#define FF 64     // features
#define WP 72     // smem pitch (floats) for B tiles -> conflict-free LDS
#define MP 36     // mask smem pitch (words)

// Scratch (device globals: allocation-free rule)
__device__ float    g_Wh[G * NN * FF];      // 16 MB (tf32-rounded)
__device__ float    g_s1[G * NN];
__device__ float    g_s2[G * NN];
__device__ uint32_t g_mask[G * NN * 32];    // 8 MB adjacency bitmasks (permuted)

__device__ __forceinline__ float f2tf32(float x) {
    float r;
    asm("cvt.rna.tf32.f32 %0, %1;" : "=f"(r) : "f"(x));
    return r;
}
__device__ __forceinline__ uint32_t smem_u32(const void* p) {
    uint32_t a;
    asm("{ .reg .u64 t; cvta.to.shared.u64 t, %1; cvt.u32.u64 %0, t; }"
        : "=r"(a) : "l"(p));
    return a;
}
#define CP_ASYNC16(dst, src) \
    asm volatile("cp.async.cg.shared.global [%0], [%1], 16;" \
                 :: "r"(dst), "l"(src) : "memory")
#define CP_COMMIT() asm volatile("cp.async.commit_group;" ::: "memory")
#define CP_WAIT(n)  asm volatile("cp.async.wait_group %0;" :: "n"(n) : "memory")

#define MMA_TF32(acc, a0, a1, a2, a3, b0, b1) \
    asm volatile( \
        "mma.sync.aligned.m16n8k8.row.col.f32.tf32.tf32.f32 " \
        "{%0,%1,%2,%3}, {%4,%5,%6,%7}, {%8,%9}, {%0,%1,%2,%3};" \
        : "+f"((acc)[0]), "+f"((acc)[1]), "+f"((acc)[2]), "+f"((acc)[3]) \
        : "r"(a0), "r"(a1), "r"(a2), "r"(a3), "r"(b0), "r"(b1))

// ---------------------------------------------------------------------------
// Kernel P (fused prep, identical to round 8):
//  blocks [0,512):    Wh = h @ W via mma.sync; s1 = Wh@a1, s2 = Wh@a2.
//  blocks [512,1536): adj -> permuted bitmask compression (int4 + ballot).
//  mask word (p,c) bit l = adj[row][p*128 + 4l + c];  stored at row*32+p*4+c.
// ---------------------------------------------------------------------------
__global__ __launch_bounds__(256) void prep_kernel(const float* __restrict__ h,
                                                   const int* __restrict__ adj,
                                                   const float* __restrict__ W,
                                                   const float* __restrict__ a) {
    __shared__ float Ws[64 * WP];
    __shared__ float sA[128];

    const int tid  = threadIdx.x;
    const int lane = tid & 31;
    const int w    = tid >> 5;

    if (blockIdx.x >= 512) {
        const int rbase = (blockIdx.x - 512) * 64 + w * 8;
        #pragma unroll 1
        for (int r = 0; r < 8; r++) {
            const int row = rbase + r;
            const int4* arow4 = (const int4*)(adj + (size_t)row * NN);
            uint32_t mval = 0;
            #pragma unroll
            for (int p = 0; p < 8; p++) {
                int4 v = arow4[p * 32 + lane];
                uint32_t b0 = __ballot_sync(0xffffffffu, v.x != 0);
                uint32_t b1 = __ballot_sync(0xffffffffu, v.y != 0);
                uint32_t b2 = __ballot_sync(0xffffffffu, v.z != 0);
                uint32_t b3 = __ballot_sync(0xffffffffu, v.w != 0);
                if (lane == p * 4 + 0) mval = b0;
                if (lane == p * 4 + 1) mval = b1;
                if (lane == p * 4 + 2) mval = b2;
                if (lane == p * 4 + 3) mval = b3;
            }
            g_mask[(size_t)row * 32 + lane] = mval;
        }
        return;
    }

    #pragma unroll
    for (int i = 0; i < 16; i++) {
        int idx = tid + i * 256;
        int k = idx >> 6, f = idx & 63;
        Ws[k * WP + f] = f2tf32(W[idx]);
    }
    if (tid < 128) sA[tid] = a[tid];
    __syncthreads();

    const int gq = lane >> 2;
    const int t  = lane & 3;
    const int r0 = blockIdx.x * 128 + w * 16 + gq;
    const int r1 = r0 + 8;
    const float* h0 = h + (size_t)r0 * FF;
    const float* h1 = h + (size_t)r1 * FF;

    float acc[8][4];
    #pragma unroll
    for (int nt = 0; nt < 8; nt++)
        #pragma unroll
        for (int q = 0; q < 4; q++) acc[nt][q] = 0.f;

    #pragma unroll
    for (int ks = 0; ks < 8; ks++) {
        const int kb = ks * 8 + t;
        const uint32_t a0 = __float_as_uint(f2tf32(h0[kb]));
        const uint32_t a1 = __float_as_uint(f2tf32(h1[kb]));
        const uint32_t a2 = __float_as_uint(f2tf32(h0[kb + 4]));
        const uint32_t a3 = __float_as_uint(f2tf32(h1[kb + 4]));
        #pragma unroll
        for (int nt = 0; nt < 8; nt++) {
            const uint32_t b0 = __float_as_uint(Ws[kb * WP + nt * 8 + gq]);
            const uint32_t b1 = __float_as_uint(Ws[(kb + 4) * WP + nt * 8 + gq]);
            MMA_TF32(acc[nt], a0, a1, a2, a3, b0, b1);
        }
    }

    float s1_0 = 0.f, s2_0 = 0.f, s1_1 = 0.f, s2_1 = 0.f;
    float* o0 = g_Wh + (size_t)r0 * FF + 2 * t;
    float* o1 = g_Wh + (size_t)r1 * FF + 2 * t;
    #pragma unroll
    for (int nt = 0; nt < 8; nt++) {
        const int c = nt * 8 + 2 * t;
        const float a1c0 = sA[c],      a1c1 = sA[c + 1];
        const float a2c0 = sA[64 + c], a2c1 = sA[64 + c + 1];
        s1_0 += acc[nt][0] * a1c0 + acc[nt][1] * a1c1;
        s2_0 += acc[nt][0] * a2c0 + acc[nt][1] * a2c1;
        s1_1 += acc[nt][2] * a1c0 + acc[nt][3] * a1c1;
        s2_1 += acc[nt][2] * a2c0 + acc[nt][3] * a2c1;
        *(float2*)(o0 + nt * 8) = make_float2(f2tf32(acc[nt][0]), f2tf32(acc[nt][1]));
        *(float2*)(o1 + nt * 8) = make_float2(f2tf32(acc[nt][2]), f2tf32(acc[nt][3]));
    }
    #pragma unroll
    for (int off = 1; off <= 2; off <<= 1) {
        s1_0 += __shfl_xor_sync(0xffffffffu, s1_0, off);
        s2_0 += __shfl_xor_sync(0xffffffffu, s2_0, off);
        s1_1 += __shfl_xor_sync(0xffffffffu, s1_1, off);
        s2_1 += __shfl_xor_sync(0xffffffffu, s2_1, off);
    }
    if (t == 0) {
        g_s1[r0] = s1_0; g_s2[r0] = s2_0;
        g_s1[r1] = s1_1; g_s2[r1] = s2_1;
    }
}

// ---------------------------------------------------------------------------
// Kernel C: out[128,64] per CTA; 128 threads, 4 warps, M=32 PER WARP
// (two m16 tiles per warp sharing B fragments). Masks smem-resident,
// factorized exp, ones-column Z, cp.async double-buffered Wh tiles.
// ---------------------------------------------------------------------------
// dynamic smem (bytes):
//  tab    float4[1024]  @ 0       (16384)
//  maskS  u32[128*MP]   @ 16384   (18432)
//  Whs0   f32[32*WP]    @ 34816   (9216)
//  Whs1   f32[32*WP]    @ 44032   (9216)   total 53248
#define OFF_TAB  0
#define OFF_MASK 16384
#define OFF_WHS0 34816
#define OFF_WHS1 44032
#define ATTN_SMEM 53248

extern __shared__ char smc[];

__global__ __launch_bounds__(128, 4) void attn_mma(float* __restrict__ out) {
    float4*   tab   = (float4*)(smc + OFF_TAB);
    uint32_t* maskS = (uint32_t*)(smc + OFF_MASK);
    const uint32_t sb = smem_u32(smc);

    const int tid  = threadIdx.x;
    const int lane = tid & 31;
    const int w    = tid >> 5;          // 0..3
    const int gq   = lane >> 2;
    const int t    = lane & 3;
    const int gr   = blockIdx.x >> 3;
    const int i0   = (blockIdx.x & 7) << 7;

    const float* Whg = g_Wh + (size_t)gr * NN * FF;

    // stage masks (row tid, 8 int4) + Wh chunk 0; build exp table
    {
        const uint32_t* msrc = g_mask + ((size_t)gr * NN + i0) * 32;
        #pragma unroll
        for (int q = 0; q < 8; q++)
            CP_ASYNC16(sb + OFF_MASK + (uint32_t)(tid * MP + q * 4) * 4,
                       msrc + tid * 32 + q * 4);
        #pragma unroll
        for (int q = 0; q < 4; q++) {
            int idx = tid + q * 128;          // 0..511
            int k = idx >> 4, s4 = (idx & 15) * 4;
            CP_ASYNC16(sb + OFF_WHS0 + (uint32_t)(k * WP + s4) * 4,
                       Whg + k * FF + s4);
        }
        CP_COMMIT();
        const float4* s2p = (const float4*)(g_s2 + (size_t)gr * NN);
        #pragma unroll
        for (int q = 0; q < 2; q++) {
            const float4 s2v = s2p[tid * 2 + q];
            tab[tid * 8 + q * 4 + 0] = make_float4(s2v.x, __expf(s2v.x), __expf(0.2f * s2v.x), 0.f);
            tab[tid * 8 + q * 4 + 1] = make_float4(s2v.y, __expf(s2v.y), __expf(0.2f * s2v.y), 0.f);
            tab[tid * 8 + q * 4 + 2] = make_float4(s2v.z, __expf(s2v.z), __expf(0.2f * s2v.z), 0.f);
            tab[tid * 8 + q * 4 + 3] = make_float4(s2v.w, __expf(s2v.w), __expf(0.2f * s2v.w), 0.f);
        }
    }

    // warp w owns rows w*32 .. w*32+31 (two m16 tiles: A=rows+0/8, B=rows+16/24)
    const int ra = w * 32 + gq;
    const int rb = ra + 8;
    const int rc = ra + 16;
    const int rd = ra + 24;
    const float* s1g = g_s1 + (size_t)gr * NN + i0;
    const float s1a = s1g[ra], s1b = s1g[rb], s1c = s1g[rc], s1d = s1g[rd];
    const float e1a = __expf(s1a), eba = __expf(0.2f * s1a), tha = -s1a;
    const float e1b = __expf(s1b), ebb = __expf(0.2f * s1b), thb = -s1b;
    const float e1c = __expf(s1c), ebc = __expf(0.2f * s1c), thc = -s1c;
    const float e1d = __expf(s1d), ebd = __expf(0.2f * s1d), thd = -s1d;

    float accA[9][4], accB[9][4];
    #pragma unroll
    for (int nt = 0; nt < 9; nt++)
        #pragma unroll
        for (int q = 0; q < 4; q++) { accA[nt][q] = 0.f; accB[nt][q] = 0.f; }
    const uint32_t bz = (gq == 0) ? 0x3f800000u : 0u;

    CP_WAIT(0);
    __syncthreads();

    const uint32_t whoff[2] = { OFF_WHS0, OFF_WHS1 };

    for (int jc = 0; jc < 32; jc++) {
        if (jc > 0) __syncthreads();
        if (jc < 31) {
            const float* srcn = Whg + (jc + 1) * 32 * FF;
            const uint32_t dstb = sb + whoff[(jc + 1) & 1];
            #pragma unroll
            for (int q = 0; q < 4; q++) {
                int idx = tid + q * 128;
                int k = idx >> 4, s4 = (idx & 15) * 4;
                CP_ASYNC16(dstb + (uint32_t)(k * WP + s4) * 4,
                           srcn + k * FF + s4);
            }
            CP_COMMIT();
            CP_WAIT(1);
        } else {
            CP_WAIT(0);
        }
        __syncthreads();

        const float* Wc = (const float*)(smc + whoff[jc & 1]);
        const int msh = (jc & 3) * 8;
        const int mw  = (jc >> 2) * 4 + t;
        const uint32_t msa = maskS[ra * MP + mw] >> msh;
        const uint32_t msb = maskS[rb * MP + mw] >> msh;
        const uint32_t msc = maskS[rc * MP + mw] >> msh;
        const uint32_t msd = maskS[rd * MP + mw] >> msh;
        const int j0 = jc * 32;

        #pragma unroll
        for (int ks = 0; ks < 4; ks++) {
            const int kb = ks * 8 + t;
            const float4 ta = tab[j0 + kb];
            const float4 tb = tab[j0 + kb + 4];

            // tile A (rows ra, rb)
            float pa0 = (ta.x > tha) ? e1a * ta.y : eba * ta.z;
            float pa1 = (tb.x > tha) ? e1a * tb.y : eba * tb.z;
            float pb0 = (ta.x > thb) ? e1b * ta.y : ebb * ta.z;
            float pb1 = (tb.x > thb) ? e1b * tb.y : ebb * tb.z;
            pa0 = (msa & (1u << (2 * ks))) ? pa0 : 0.f;
            pa1 = (msa & (2u << (2 * ks))) ? pa1 : 0.f;
            pb0 = (msb & (1u << (2 * ks))) ? pb0 : 0.f;
            pb1 = (msb & (2u << (2 * ks))) ? pb1 : 0.f;
            // tile B (rows rc, rd)
            float pc0 = (ta.x > thc) ? e1c * ta.y : ebc * ta.z;
            float pc1 = (tb.x > thc) ? e1c * tb.y : ebc * tb.z;
            float pd0 = (ta.x > thd) ? e1d * ta.y : ebd * ta.z;
            float pd1 = (tb.x > thd) ? e1d * tb.y : ebd * tb.z;
            pc0 = (msc & (1u << (2 * ks))) ? pc0 : 0.f;
            pc1 = (msc & (2u << (2 * ks))) ? pc1 : 0.f;
            pd0 = (msd & (1u << (2 * ks))) ? pd0 : 0.f;
            pd1 = (msd & (2u << (2 * ks))) ? pd1 : 0.f;

            const uint32_t aA0 = __float_as_uint(pa0);
            const uint32_t aA1 = __float_as_uint(pb0);
            const uint32_t aA2 = __float_as_uint(pa1);
            const uint32_t aA3 = __float_as_uint(pb1);
            const uint32_t aB0 = __float_as_uint(pc0);
            const uint32_t aB1 = __float_as_uint(pd0);
            const uint32_t aB2 = __float_as_uint(pc1);
            const uint32_t aB3 = __float_as_uint(pd1);

            #pragma unroll
            for (int nt = 0; nt < 8; nt++) {
                const uint32_t b0 = __float_as_uint(Wc[kb * WP + nt * 8 + gq]);
                const uint32_t b1 = __float_as_uint(Wc[(kb + 4) * WP + nt * 8 + gq]);
                MMA_TF32(accA[nt], aA0, aA1, aA2, aA3, b0, b1);
                MMA_TF32(accB[nt], aB0, aB1, aB2, aB3, b0, b1);
            }
            MMA_TF32(accA[8], aA0, aA1, aA2, aA3, bz, bz);
            MMA_TF32(accB[8], aB0, aB1, aB2, aB3, bz, bz);
        }
    }

    // Z per row (ones tile, t==0 lanes hold col 64)
    const float Za = __shfl_sync(0xffffffffu, accA[8][0], lane & 28);
    const float Zb = __shfl_sync(0xffffffffu, accA[8][2], lane & 28);
    const float Zc = __shfl_sync(0xffffffffu, accB[8][0], lane & 28);
    const float Zd = __shfl_sync(0xffffffffu, accB[8][2], lane & 28);
    const float iva = 1.0f / Za, ivb = 1.0f / Zb;
    const float ivc = 1.0f / Zc, ivd = 1.0f / Zd;

    float* oa = out + ((size_t)gr * NN + i0 + ra) * FF + 2 * t;
    float* ob = out + ((size_t)gr * NN + i0 + rb) * FF + 2 * t;
    float* oc = out + ((size_t)gr * NN + i0 + rc) * FF + 2 * t;
    float* od = out + ((size_t)gr * NN + i0 + rd) * FF + 2 * t;
    #pragma unroll
    for (int nt = 0; nt < 8; nt++) {
        float e0 = accA[nt][0] * iva, e1 = accA[nt][1] * iva;
        float e2 = accA[nt][2] * ivb, e3 = accA[nt][3] * ivb;
        float e4 = accB[nt][0] * ivc, e5 = accB[nt][1] * ivc;
        float e6 = accB[nt][2] * ivd, e7 = accB[nt][3] * ivd;
        e0 = e0 > 0.f ? e0 : expm1f(e0);  e1 = e1 > 0.f ? e1 : expm1f(e1);
        e2 = e2 > 0.f ? e2 : expm1f(e2);  e3 = e3 > 0.f ? e3 : expm1f(e3);
        e4 = e4 > 0.f ? e4 : expm1f(e4);  e5 = e5 > 0.f ? e5 : expm1f(e5);
        e6 = e6 > 0.f ? e6 : expm1f(e6);  e7 = e7 > 0.f ? e7 : expm1f(e7);
        *(float2*)(oa + nt * 8) = make_float2(e0, e1);
        *(float2*)(ob + nt * 8) = make_float2(e2, e3);
        *(float2*)(oc + nt * 8) = make_float2(e4, e5);
        *(float2*)(od + nt * 8) = make_float2(e6, e7);
    }
}

// ---------------------------------------------------------------------------
extern "C" void kernel_launch(void* const* d_in, const int* in_sizes, int n_in,
                              void* d_out, int out_size) {
    const float* h   = (const float*)d_in[0];
    const int*   adj = (const int*)d_in[1];
    const float* W   = (const float*)d_in[2];
    const float* a   = (const float*)d_in[3];
    float* out = (float*)d_out;

    cudaFuncSetAttribute(attn_mma, cudaFuncAttributeMaxDynamicSharedMemorySize,
                         ATTN_SMEM);

    prep_kernel<<<512 + 1024, 256>>>(h, adj, W, a);
    attn_mma<<<G * 8, 128, ATTN_SMEM>>>(out);
}

// round 13
// speedup vs baseline: 1.4884x; 1.2646x over previous
#include <cuda_runtime.h>
#include <cuda_fp16.h>
#include <math.h>
#include <stdint.h>

#define G 64      // B*T graphs
#define NN 1024   // nodes per graph
#define FF 64     // features
#define WP 72     // smem pitch (floats) for prep W tile
#define MP 36     // mask smem pitch (words)

// Scratch (device globals: allocation-free rule)
__device__ __half   g_WhhT[G * FF * NN];    // 8 MB, [g][f][j'] fp16, j-permuted
__device__ float    g_s1[G * NN];
__device__ __half   g_yh[G * NN];           // e^{s2}/16  at permuted index
__device__ __half   g_zh[G * NN];           // e^{0.2 s2}/16
__device__ __half   g_s2h[G * NN];          // s2 (for branch compare)
__device__ uint32_t g_mask[G * NN * 32];    // adjacency bitmasks (permuted)

__device__ __forceinline__ float f2tf32(float x) {
    float r;
    asm("cvt.rna.tf32.f32 %0, %1;" : "=f"(r) : "f"(x));
    return r;
}
__device__ __forceinline__ uint32_t smem_u32(const void* p) {
    uint32_t a;
    asm("{ .reg .u64 t; cvta.to.shared.u64 t, %1; cvt.u32.u64 %0, t; }"
        : "=r"(a) : "l"(p));
    return a;
}
__device__ __forceinline__ uint32_t packh2(float x) {
    __half h = __float2half_rn(x);
    uint32_t u = (uint32_t)__half_as_ushort(h);
    return u | (u << 16);
}
__device__ __forceinline__ uint32_t hgt2m(uint32_t a, uint32_t b) {
    uint32_t d;
    asm("set.gt.u32.f16x2 %0, %1, %2;" : "=r"(d) : "r"(a), "r"(b));
    return d;
}
__device__ __forceinline__ uint32_t hmul2u(uint32_t a, uint32_t b) {
    uint32_t d;
    asm("mul.rn.f16x2 %0, %1, %2;" : "=r"(d) : "r"(a), "r"(b));
    return d;
}
#define CP_ASYNC16(dst, src) \
    asm volatile("cp.async.cg.shared.global [%0], [%1], 16;" \
                 :: "r"(dst), "l"(src) : "memory")
#define CP_COMMIT() asm volatile("cp.async.commit_group;" ::: "memory")
#define CP_WAIT(n)  asm volatile("cp.async.wait_group %0;" :: "n"(n) : "memory")

#define MMA_TF32(acc, a0, a1, a2, a3, b0, b1) \
    asm volatile( \
        "mma.sync.aligned.m16n8k8.row.col.f32.tf32.tf32.f32 " \
        "{%0,%1,%2,%3}, {%4,%5,%6,%7}, {%8,%9}, {%0,%1,%2,%3};" \
        : "+f"((acc)[0]), "+f"((acc)[1]), "+f"((acc)[2]), "+f"((acc)[3]) \
        : "r"(a0), "r"(a1), "r"(a2), "r"(a3), "r"(b0), "r"(b1))

#define MMA_FP16(acc, a0, a1, a2, a3, b0, b1) \
    asm volatile( \
        "mma.sync.aligned.m16n8k16.row.col.f32.f16.f16.f32 " \
        "{%0,%1,%2,%3}, {%4,%5,%6,%7}, {%8,%9}, {%0,%1,%2,%3};" \
        : "+f"((acc)[0]), "+f"((acc)[1]), "+f"((acc)[2]), "+f"((acc)[3]) \
        : "r"(a0), "r"(a1), "r"(a2), "r"(a3), "r"(b0), "r"(b1))

// permuted j index: j = p*128 + 4*pos + c  ->  j' = (p*4+c)*32 + pos
__device__ __forceinline__ int permIdx(int j) {
    int jc  = ((j >> 7) << 2) | (j & 3);
    int pos = (j & 127) >> 2;
    return jc * 32 + pos;
}

// ---------------------------------------------------------------------------
// Kernel P (fused prep):
//  blocks [0,512):    Wh = h @ W via tf32 mma; store WhhT fp16 (transposed,
//                     j-permuted); s1 fp32; yh/zh/s2h fp16 (permuted).
//  blocks [512,1536): adj -> permuted bitmask compression (int4 + ballot).
// ---------------------------------------------------------------------------
__global__ __launch_bounds__(256) void prep_kernel(const float* __restrict__ h,
                                                   const int* __restrict__ adj,
                                                   const float* __restrict__ W,
                                                   const float* __restrict__ a) {
    __shared__ float Ws[64 * WP];
    __shared__ float sA[128];

    const int tid  = threadIdx.x;
    const int lane = tid & 31;
    const int w    = tid >> 5;

    if (blockIdx.x >= 512) {
        const int rbase = (blockIdx.x - 512) * 64 + w * 8;
        #pragma unroll 2
        for (int r = 0; r < 8; r++) {
            const int row = rbase + r;
            const int4* arow4 = (const int4*)(adj + (size_t)row * NN);
            uint32_t mval = 0;
            #pragma unroll
            for (int p = 0; p < 8; p++) {
                int4 v = arow4[p * 32 + lane];
                uint32_t b0 = __ballot_sync(0xffffffffu, v.x != 0);
                uint32_t b1 = __ballot_sync(0xffffffffu, v.y != 0);
                uint32_t b2 = __ballot_sync(0xffffffffu, v.z != 0);
                uint32_t b3 = __ballot_sync(0xffffffffu, v.w != 0);
                if (lane == p * 4 + 0) mval = b0;
                if (lane == p * 4 + 1) mval = b1;
                if (lane == p * 4 + 2) mval = b2;
                if (lane == p * 4 + 3) mval = b3;
            }
            g_mask[(size_t)row * 32 + lane] = mval;
        }
        return;
    }

    #pragma unroll
    for (int i = 0; i < 16; i++) {
        int idx = tid + i * 256;
        int k = idx >> 6, f = idx & 63;
        Ws[k * WP + f] = f2tf32(W[idx]);
    }
    if (tid < 128) sA[tid] = a[tid];
    __syncthreads();

    const int gq = lane >> 2;
    const int t  = lane & 3;
    const int r0 = blockIdx.x * 128 + w * 16 + gq;
    const int r1 = r0 + 8;
    const float* h0 = h + (size_t)r0 * FF;
    const float* h1 = h + (size_t)r1 * FF;

    float acc[8][4];
    #pragma unroll
    for (int nt = 0; nt < 8; nt++)
        #pragma unroll
        for (int q = 0; q < 4; q++) acc[nt][q] = 0.f;

    #pragma unroll
    for (int ks = 0; ks < 8; ks++) {
        const int kb = ks * 8 + t;
        const uint32_t a0 = __float_as_uint(f2tf32(h0[kb]));
        const uint32_t a1 = __float_as_uint(f2tf32(h1[kb]));
        const uint32_t a2 = __float_as_uint(f2tf32(h0[kb + 4]));
        const uint32_t a3 = __float_as_uint(f2tf32(h1[kb + 4]));
        #pragma unroll
        for (int nt = 0; nt < 8; nt++) {
            const uint32_t b0 = __float_as_uint(Ws[kb * WP + nt * 8 + gq]);
            const uint32_t b1 = __float_as_uint(Ws[(kb + 4) * WP + nt * 8 + gq]);
            MMA_TF32(acc[nt], a0, a1, a2, a3, b0, b1);
        }
    }

    // stores: WhhT fp16 (transposed + j-permuted) and s-dots
    const int grk = r0 >> 10;
    const int pi0 = permIdx(r0 & 1023);
    const int pi1 = permIdx(r1 & 1023);
    __half* WT = g_WhhT + (size_t)grk * (FF * NN);

    float s1_0 = 0.f, s2_0 = 0.f, s1_1 = 0.f, s2_1 = 0.f;
    #pragma unroll
    for (int nt = 0; nt < 8; nt++) {
        const int c = nt * 8 + 2 * t;
        const float a1c0 = sA[c],      a1c1 = sA[c + 1];
        const float a2c0 = sA[64 + c], a2c1 = sA[64 + c + 1];
        s1_0 += acc[nt][0] * a1c0 + acc[nt][1] * a1c1;
        s2_0 += acc[nt][0] * a2c0 + acc[nt][1] * a2c1;
        s1_1 += acc[nt][2] * a1c0 + acc[nt][3] * a1c1;
        s2_1 += acc[nt][2] * a2c0 + acc[nt][3] * a2c1;
        WT[(c + 0) * NN + pi0] = __float2half_rn(acc[nt][0]);
        WT[(c + 1) * NN + pi0] = __float2half_rn(acc[nt][1]);
        WT[(c + 0) * NN + pi1] = __float2half_rn(acc[nt][2]);
        WT[(c + 1) * NN + pi1] = __float2half_rn(acc[nt][3]);
    }
    #pragma unroll
    for (int off = 1; off <= 2; off <<= 1) {
        s1_0 += __shfl_xor_sync(0xffffffffu, s1_0, off);
        s2_0 += __shfl_xor_sync(0xffffffffu, s2_0, off);
        s1_1 += __shfl_xor_sync(0xffffffffu, s1_1, off);
        s2_1 += __shfl_xor_sync(0xffffffffu, s2_1, off);
    }
    if (t == 0) {
        g_s1[r0] = s1_0;
        g_s1[r1] = s1_1;
        const int gb = grk * NN;
        g_s2h[gb + pi0] = __float2half_rn(s2_0);
        g_s2h[gb + pi1] = __float2half_rn(s2_1);
        g_yh[gb + pi0]  = __float2half_rn(__expf(s2_0) * 0.0625f);
        g_yh[gb + pi1]  = __float2half_rn(__expf(s2_1) * 0.0625f);
        g_zh[gb + pi0]  = __float2half_rn(__expf(0.2f * s2_0) * 0.0625f);
        g_zh[gb + pi1]  = __float2half_rn(__expf(0.2f * s2_1) * 0.0625f);
    }
}

// ---------------------------------------------------------------------------
// Kernel C: out[128,64] per CTA, fp16 mma m16n8k16 over permuted j.
// 128 thr, 4 warps x M=32. p' = p * e^{-s1}/16 (row scale cancels in softmax):
//   pos: p' = y_j = e^{s2}/16;  neg: p' = rh_i * z_j, rh = e^{-0.8 s1}.
// Packed half2 P-gen (set.gt mask + LOP3 select + adjacency LUT-AND).
// Z via ones-column MMA tile. Wh tiles cp.async double-buffered.
// ---------------------------------------------------------------------------
__global__ __launch_bounds__(128, 4) void attn_mma(float* __restrict__ out) {
    __shared__ uint32_t yh2s[512];          // 2 KB
    __shared__ uint32_t zh2s[512];          // 2 KB
    __shared__ uint32_t s2h2s[512];         // 2 KB
    __shared__ uint32_t lutS[4];
    __shared__ uint32_t maskS[128 * MP];    // 18.4 KB
    __shared__ char     whbuf[2][64 * 80];  // 10 KB, [f][j'] fp16 pitch 80B

    const int tid  = threadIdx.x;
    const int lane = tid & 31;
    const int w    = tid >> 5;
    const int gq   = lane >> 2;
    const int t    = lane & 3;
    const int gr   = blockIdx.x >> 3;
    const int i0   = (blockIdx.x & 7) << 7;

    if (tid < 4)
        lutS[tid] = ((tid & 1) ? 0x0000FFFFu : 0u) | ((tid & 2) ? 0xFFFF0000u : 0u);

    const uint32_t sbY = smem_u32(yh2s);
    const uint32_t sbZ = smem_u32(zh2s);
    const uint32_t sbS = smem_u32(s2h2s);
    const uint32_t sbM = smem_u32(maskS);
    const uint32_t sbW0 = smem_u32(&whbuf[0][0]);
    const uint32_t sbW1 = smem_u32(&whbuf[1][0]);
    const uint32_t whoff[2] = { sbW0, sbW1 };

    const char* WTg = (const char*)(g_WhhT + (size_t)gr * (FF * NN));

    // ---- prologue staging (one cp.async group)
    {
        const char* ys = (const char*)(g_yh  + (size_t)gr * NN);
        const char* zs = (const char*)(g_zh  + (size_t)gr * NN);
        const char* ss = (const char*)(g_s2h + (size_t)gr * NN);
        CP_ASYNC16(sbY + tid * 16, ys + tid * 16);
        CP_ASYNC16(sbZ + tid * 16, zs + tid * 16);
        CP_ASYNC16(sbS + tid * 16, ss + tid * 16);
        const char* ms = (const char*)(g_mask + ((size_t)gr * NN + i0) * 32);
        #pragma unroll
        for (int q = 0; q < 8; q++) {
            int idx = tid + q * 128;            // 0..1023
            int r = idx >> 3, s = idx & 7;
            CP_ASYNC16(sbM + (uint32_t)(r * 144 + s * 16), ms + r * 128 + s * 16);
        }
        #pragma unroll
        for (int q = 0; q < 2; q++) {
            int idx = tid + q * 128;            // 0..255
            int f = idx >> 2, sg = idx & 3;
            CP_ASYNC16(sbW0 + (uint32_t)(f * 80 + sg * 16),
                       WTg + f * 2048 + sg * 16);
        }
        CP_COMMIT();
    }

    // ---- per-row constants (4 rows per thread)
    const int ra = w * 32 + gq;
    const int rb = ra + 8, rc = ra + 16, rd = ra + 24;
    const float* s1g = g_s1 + (size_t)gr * NN + i0;
    const float s1A = s1g[ra], s1B = s1g[rb], s1C = s1g[rc], s1D = s1g[rd];
    const uint32_t nA = packh2(-s1A), rhA = packh2(__expf(-0.8f * s1A));
    const uint32_t nB = packh2(-s1B), rhB = packh2(__expf(-0.8f * s1B));
    const uint32_t nC = packh2(-s1C), rhC = packh2(__expf(-0.8f * s1C));
    const uint32_t nD = packh2(-s1D), rhD = packh2(__expf(-0.8f * s1D));

    float accA[9][4], accB[9][4];
    #pragma unroll
    for (int nt = 0; nt < 9; nt++)
        #pragma unroll
        for (int q = 0; q < 4; q++) { accA[nt][q] = 0.f; accB[nt][q] = 0.f; }
    const uint32_t bz = (gq == 0) ? 0x3C003C00u : 0u;   // ones-col B frag

    CP_WAIT(0);
    __syncthreads();

    for (int jc = 0; jc < 32; jc++) {
        if (jc > 0) __syncthreads();
        if (jc < 31) {
            const uint32_t dstb = whoff[(jc + 1) & 1];
            const int joff = (jc + 1) * 64;     // byte offset within f-row
            #pragma unroll
            for (int q = 0; q < 2; q++) {
                int idx = tid + q * 128;
                int f = idx >> 2, sg = idx & 3;
                CP_ASYNC16(dstb + (uint32_t)(f * 80 + sg * 16),
                           WTg + f * 2048 + joff + sg * 16);
            }
            CP_COMMIT();
            CP_WAIT(1);
        } else {
            CP_WAIT(0);
        }
        __syncthreads();

        const uint32_t* wb = (const uint32_t*)(jc & 1 ? &whbuf[1][0] : &whbuf[0][0]);
        const uint32_t mA = maskS[ra * MP + jc] >> (2 * t);
        const uint32_t mB = maskS[rb * MP + jc] >> (2 * t);
        const uint32_t mC = maskS[rc * MP + jc] >> (2 * t);
        const uint32_t mD = maskS[rd * MP + jc] >> (2 * t);
        const int tb = jc * 16 + t;

        #pragma unroll
        for (int ks = 0; ks < 2; ks++) {
            const int u0 = tb + ks * 8;         // fp16x2 unit for jpA
            const uint32_t y0 = yh2s[u0],     y1 = yh2s[u0 + 4];
            const uint32_t z0 = zh2s[u0],     z1 = zh2s[u0 + 4];
            const uint32_t s0 = s2h2s[u0],    s1p = s2h2s[u0 + 4];
            const int shA = ks * 16, shB = ks * 16 + 8;

            // row A
            uint32_t cm0 = hgt2m(s0, nA), cm1 = hgt2m(s1p, nA);
            uint32_t zz0 = hmul2u(z0, rhA), zz1 = hmul2u(z1, rhA);
            uint32_t pA0 = ((y0 & cm0) | (zz0 & ~cm0)) & lutS[(mA >> shA) & 3];
            uint32_t pA1 = ((y1 & cm1) | (zz1 & ~cm1)) & lutS[(mA >> shB) & 3];
            // row B
            cm0 = hgt2m(s0, nB); cm1 = hgt2m(s1p, nB);
            zz0 = hmul2u(z0, rhB); zz1 = hmul2u(z1, rhB);
            uint32_t pB0 = ((y0 & cm0) | (zz0 & ~cm0)) & lutS[(mB >> shA) & 3];
            uint32_t pB1 = ((y1 & cm1) | (zz1 & ~cm1)) & lutS[(mB >> shB) & 3];
            // row C
            cm0 = hgt2m(s0, nC); cm1 = hgt2m(s1p, nC);
            zz0 = hmul2u(z0, rhC); zz1 = hmul2u(z1, rhC);
            uint32_t pC0 = ((y0 & cm0) | (zz0 & ~cm0)) & lutS[(mC >> shA) & 3];
            uint32_t pC1 = ((y1 & cm1) | (zz1 & ~cm1)) & lutS[(mC >> shB) & 3];
            // row D
            cm0 = hgt2m(s0, nD); cm1 = hgt2m(s1p, nD);
            zz0 = hmul2u(z0, rhD); zz1 = hmul2u(z1, rhD);
            uint32_t pD0 = ((y0 & cm0) | (zz0 & ~cm0)) & lutS[(mD >> shA) & 3];
            uint32_t pD1 = ((y1 & cm1) | (zz1 & ~cm1)) & lutS[(mD >> shB) & 3];

            const int rbw = gq * 20 + ks * 8 + t;   // B word base
            #pragma unroll
            for (int nt = 0; nt < 8; nt++) {
                const uint32_t b0 = wb[nt * 160 + rbw];
                const uint32_t b1 = wb[nt * 160 + rbw + 4];
                MMA_FP16(accA[nt], pA0, pB0, pA1, pB1, b0, b1);
                MMA_FP16(accB[nt], pC0, pD0, pC1, pD1, b0, b1);
            }
            MMA_FP16(accA[8], pA0, pB0, pA1, pB1, bz, bz);   // Z tile
            MMA_FP16(accB[8], pC0, pD0, pC1, pD1, bz, bz);
        }
    }

    // Z per row (ones tile col 0, held by t==0 lanes)
    const float Za = __shfl_sync(0xffffffffu, accA[8][0], lane & 28);
    const float Zb = __shfl_sync(0xffffffffu, accA[8][2], lane & 28);
    const float Zc = __shfl_sync(0xffffffffu, accB[8][0], lane & 28);
    const float Zd = __shfl_sync(0xffffffffu, accB[8][2], lane & 28);
    const float iva = 1.0f / Za, ivb = 1.0f / Zb;
    const float ivc = 1.0f / Zc, ivd = 1.0f / Zd;

    float* oa = out + ((size_t)gr * NN + i0 + ra) * FF + 2 * t;
    float* ob = out + ((size_t)gr * NN + i0 + rb) * FF + 2 * t;
    float* oc = out + ((size_t)gr * NN + i0 + rc) * FF + 2 * t;
    float* od = out + ((size_t)gr * NN + i0 + rd) * FF + 2 * t;
    #pragma unroll
    for (int nt = 0; nt < 8; nt++) {
        float e0 = accA[nt][0] * iva, e1 = accA[nt][1] * iva;
        float e2 = accA[nt][2] * ivb, e3 = accA[nt][3] * ivb;
        float e4 = accB[nt][0] * ivc, e5 = accB[nt][1] * ivc;
        float e6 = accB[nt][2] * ivd, e7 = accB[nt][3] * ivd;
        e0 = e0 > 0.f ? e0 : expm1f(e0);  e1 = e1 > 0.f ? e1 : expm1f(e1);
        e2 = e2 > 0.f ? e2 : expm1f(e2);  e3 = e3 > 0.f ? e3 : expm1f(e3);
        e4 = e4 > 0.f ? e4 : expm1f(e4);  e5 = e5 > 0.f ? e5 : expm1f(e5);
        e6 = e6 > 0.f ? e6 : expm1f(e6);  e7 = e7 > 0.f ? e7 : expm1f(e7);
        *(float2*)(oa + nt * 8) = make_float2(e0, e1);
        *(float2*)(ob + nt * 8) = make_float2(e2, e3);
        *(float2*)(oc + nt * 8) = make_float2(e4, e5);
        *(float2*)(od + nt * 8) = make_float2(e6, e7);
    }
}

// ---------------------------------------------------------------------------
extern "C" void kernel_launch(void* const* d_in, const int* in_sizes, int n_in,
                              void* d_out, int out_size) {
    const float* h   = (const float*)d_in[0];
    const int*   adj = (const int*)d_in[1];
    const float* W   = (const float*)d_in[2];
    const float* a   = (const float*)d_in[3];
    float* out = (float*)d_out;

    prep_kernel<<<512 + 1024, 256>>>(h, adj, W, a);
    attn_mma<<<G * 8, 128>>>(out);
}